// round 6
// baseline (speedup 1.0000x reference)
#include <cuda_runtime.h>
#include <cstdint>
#include <math.h>

#define NN 384
#define HH 768
#define NB 576                              // 4 blocks/SM x 144; <= 592 co-resident
#define INV_SQRT_H 0.03608439182435161f     // 1/sqrt(768)
#define INV_N      0.0026041666666666665f   // 1/384

struct Coef { float c[7]; };                // odd-poly tanh coeffs (s-basis, s=x/4)

// ---------------- scratch (device globals; no allocation allowed) ----------
__device__ float g_P [4 * NN * NN];         // k-split tanh-sum partials   2.25 MB
__device__ float g_E [NN * NN];             // exp(att)                    576 KB
__device__ float g_ET[NN * NN];             // exp(att) transposed         576 KB
__device__ float g_rinv[NN], g_cinv[NN];
__device__ float g_a[NN], g_b[NN];
__device__ float g_w_hypo[NN], g_w_hyper[NN];
__device__ float g_hpart[64 * HH], g_xpart[64 * HH];
__device__ float g_hp[HH], g_xp[HH];
__device__ unsigned g_arrive;               // monotonic barrier counter (replay-safe)

// ---------------- f16x2 helpers ----------------
__device__ __forceinline__ uint32_t packh2(float a, float b) {
    uint32_t d;
    asm("cvt.rn.f16x2.f32 %0, %1, %2;" : "=r"(d) : "f"(b), "f"(a));
    return d;
}
__device__ __forceinline__ uint32_t hmul2(uint32_t a, uint32_t b) {
    uint32_t d;
    asm("mul.rn.f16x2 %0, %1, %2;" : "=r"(d) : "r"(a), "r"(b));
    return d;
}
__device__ __forceinline__ uint32_t hadd2(uint32_t a, uint32_t b) {
    uint32_t d;
    asm("add.rn.f16x2 %0, %1, %2;" : "=r"(d) : "r"(a), "r"(b));
    return d;
}
__device__ __forceinline__ uint32_t htanh2(uint32_t a) {
    uint32_t d;
    asm("tanh.approx.f16x2 %0, %1;" : "=r"(d) : "r"(a));
    return d;
}
__device__ __forceinline__ float h2sum(uint32_t s) {
    float lo, hi;
    asm("{ .reg .b16 l, h;\n\t"
        "  mov.b32 {l, h}, %2;\n\t"
        "  cvt.f32.f16 %0, l;\n\t"
        "  cvt.f32.f16 %1, h; }"
        : "=f"(lo), "=f"(hi) : "r"(s));
    return lo + hi;
}

__device__ __forceinline__ float warp_sum(float v) {
    #pragma unroll
    for (int o = 16; o; o >>= 1) v += __shfl_xor_sync(0xffffffffu, v, o);
    return v;
}

// Software grid barrier. Monotonic counter -> safe across CUDA-graph replays.
__device__ __forceinline__ void grid_barrier() {
    __syncthreads();
    __threadfence();
    if (threadIdx.x == 0) {
        unsigned my = atomicAdd(&g_arrive, 1u) + 1u;
        unsigned target = ((my + NB - 1u) / NB) * NB;
        unsigned cur;
        do {
            asm volatile("ld.global.acquire.gpu.b32 %0, [%1];"
                         : "=r"(cur) : "l"(&g_arrive));
        } while ((int)(cur - target) < 0);
    }
    __syncthreads();
    __threadfence();
}

// ---------------- single fused kernel ----------------------------------------
__global__ __launch_bounds__(256, 4) void fused_kernel(const float* __restrict__ X,
                                                       const float* __restrict__ Y,
                                                       const float* __restrict__ W,
                                                       const float* __restrict__ B,
                                                       float* __restrict__ out,
                                                       Coef cf) {
    __shared__ float    sXf[32][33];    // X tile, PRESCALED by 0.25 (poly path only)
    __shared__ float    sYf[32][33];    // Y tile, unscaled f32 (poly path only)
    __shared__ uint32_t sX2[32][17];    // f16x2-packed tiles (tanh2 path)
    __shared__ uint32_t sY2[32][17];

    const int tid = threadIdx.x;
    const int lane = tid & 31;
    const int wid = tid >> 5;

    const float c0 = cf.c[0], c1 = cf.c[1], c2 = cf.c[2], c3 = cf.c[3];
    const float c4 = cf.c[4], c5 = cf.c[5], c6 = cf.c[6];

    // ===== Phase 0: k-split partials of sum_h tanh(X[n,h]*Y[m,h]) ===========
    // 576 blocks = 144 tiles (32x32) x 4 k-chunks of 192. 16x16 threads, 2x2 micro.
    // k-offsets 0..21 of each 32-chunk: hw tanh2 (XU pipe, f16x2).
    // k-offsets 22..31: f32 odd-poly tanh on the FMA pipe (XU was the bottleneck).
    {
        const int tile = blockIdx.x % 144;
        const int kc   = blockIdx.x / 144;       // 0..3
        const int tx = tid & 15;
        const int ty = tid >> 4;
        const int bi = (tile / 12) * 32;         // hypo rows
        const int bj = (tile % 12) * 32;         // hyper rows
        const int lr = tid >> 3;                 // 0..31 load row
        const int lf = (tid & 7) << 2;           // float offset 0..28
        const int lh = (tid & 7) << 1;           // half2 offset 0..14

        float a00 = 0.f, a01 = 0.f, a10 = 0.f, a11 = 0.f;

        const int kbeg = kc * 192, kend = kbeg + 192;
        #pragma unroll 1
        for (int k0 = kbeg; k0 < kend; k0 += 32) {
            float4 vx = *(const float4*)(X + (size_t)(bi + lr) * HH + k0 + lf);
            float4 vy = *(const float4*)(Y + (size_t)(bj + lr) * HH + k0 + lf);
            sXf[lr][lf + 0] = vx.x * 0.25f; sXf[lr][lf + 1] = vx.y * 0.25f;
            sXf[lr][lf + 2] = vx.z * 0.25f; sXf[lr][lf + 3] = vx.w * 0.25f;
            sYf[lr][lf + 0] = vy.x; sYf[lr][lf + 1] = vy.y;
            sYf[lr][lf + 2] = vy.z; sYf[lr][lf + 3] = vy.w;
            sX2[lr][lh]     = packh2(vx.x, vx.y);
            sX2[lr][lh + 1] = packh2(vx.z, vx.w);
            sY2[lr][lh]     = packh2(vy.x, vy.y);
            sY2[lr][lh + 1] = packh2(vy.z, vy.w);
            __syncthreads();

            // --- hw-tanh2 lanes: kk = 0..10 (k-offsets 0..21) ---
            uint32_t ch00 = 0, ch01 = 0, ch10 = 0, ch11 = 0;   // chain A (even kk)
            uint32_t cd00 = 0, cd01 = 0, cd10 = 0, cd11 = 0;   // chain B (odd kk)
            #pragma unroll
            for (int kk = 0; kk < 11; kk++) {
                uint32_t x0 = sX2[2 * ty][kk],     x1 = sX2[2 * ty + 1][kk];
                uint32_t y0 = sY2[2 * tx][kk],     y1 = sY2[2 * tx + 1][kk];
                if (kk & 1) {
                    cd00 = hadd2(cd00, htanh2(hmul2(x0, y0)));
                    cd01 = hadd2(cd01, htanh2(hmul2(x0, y1)));
                    cd10 = hadd2(cd10, htanh2(hmul2(x1, y0)));
                    cd11 = hadd2(cd11, htanh2(hmul2(x1, y1)));
                } else {
                    ch00 = hadd2(ch00, htanh2(hmul2(x0, y0)));
                    ch01 = hadd2(ch01, htanh2(hmul2(x0, y1)));
                    ch10 = hadd2(ch10, htanh2(hmul2(x1, y0)));
                    ch11 = hadd2(ch11, htanh2(hmul2(x1, y1)));
                }
            }
            a00 += h2sum(hadd2(ch00, cd00));
            a01 += h2sum(hadd2(ch01, cd01));
            a10 += h2sum(hadd2(ch10, cd10));
            a11 += h2sum(hadd2(ch11, cd11));

            // --- poly lanes: k-offsets 22..31 (f32, FMA pipe) ---
            #pragma unroll
            for (int k = 22; k < 32; k++) {
                float x0 = sXf[2 * ty][k], x1 = sXf[2 * ty + 1][k];   // prescaled x/4
                float y0 = sYf[2 * tx][k], y1 = sYf[2 * tx + 1][k];
                #define POLY_ACC(acc, xx, yy) do {                         \
                    float s_ = fminf(fmaxf((xx) * (yy), -1.0f), 1.0f);     \
                    float v_ = s_ * s_;                                    \
                    float H_ = c6;                                         \
                    H_ = fmaf(H_, v_, c5); H_ = fmaf(H_, v_, c4);          \
                    H_ = fmaf(H_, v_, c3); H_ = fmaf(H_, v_, c2);          \
                    H_ = fmaf(H_, v_, c1); H_ = fmaf(H_, v_, c0);          \
                    (acc) = fmaf(H_, s_, (acc));                           \
                } while (0)
                POLY_ACC(a00, x0, y0);
                POLY_ACC(a01, x0, y1);
                POLY_ACC(a10, x1, y0);
                POLY_ACC(a11, x1, y1);
                #undef POLY_ACC
            }
            __syncthreads();
        }

        float* P = g_P + (size_t)kc * NN * NN;
        const int i = bi + 2 * ty, j = bj + 2 * tx;
        P[i * NN + j]           = a00;
        P[i * NN + j + 1]       = a01;
        P[(i + 1) * NN + j]     = a10;
        P[(i + 1) * NN + j + 1] = a11;
    }
    grid_barrier();

    // ===== Phase 0.5: combine k-partials -> E = exp(att), plus transpose ====
    {
        const int idx = blockIdx.x * 256 + tid;      // exactly covers 384*384
        float s = g_P[idx] + g_P[NN * NN + idx] + g_P[2 * NN * NN + idx] + g_P[3 * NN * NN + idx];
        float e = __expf(s * INV_SQRT_H);            // |att|<=27.7 -> fp32-safe
        g_E[idx] = e;
        const int i = idx / NN, j = idx - (idx / NN) * NN;
        g_ET[j * NN + i] = e;
    }
    grid_barrier();

    const int gw = blockIdx.x * 8 + wid;     // global warp id

    // ===== P1: inverse row/col sums of E (warp per row; coalesced) ==========
    if (gw < 2 * NN) {
        const float* row = (gw < NN) ? (g_E + gw * NN) : (g_ET + (gw - NN) * NN);
        float s = 0.f;
        #pragma unroll
        for (int l = 0; l < 12; l++) s += row[lane + 32 * l];
        s = warp_sum(s);
        if (lane == 0) {
            if (gw < NN) g_rinv[gw] = 1.0f / s;
            else         g_cinv[gw - NN] = 1.0f / s;
        }
    }
    grid_barrier();

    // ===== P2: typicalness factors (pre-scaled) ==============================
    if (gw < 2 * NN) {
        float s = 0.f;
        if (gw < NN) {
            const float* row = g_E + gw * NN;
            #pragma unroll
            for (int l = 0; l < 12; l++) {
                int m = lane + 32 * l;
                s += row[m] * g_cinv[m];
            }
            s = warp_sum(s);
            if (lane == 0) g_b[gw] = s * g_rinv[gw] * INV_N;
        } else {
            const int c = gw - NN;
            const float* row = g_ET + c * NN;
            #pragma unroll
            for (int l = 0; l < 12; l++) {
                int n = lane + 32 * l;
                s += row[n] * g_rinv[n];
            }
            s = warp_sum(s);
            if (lane == 0) g_a[c] = s * g_cinv[c] * INV_N;
        }
    }
    grid_barrier();

    // ===== P3: pooling weights ===============================================
    if (gw < 2 * NN) {
        float s = 0.f;
        if (gw < NN) {
            const float* row = g_E + gw * NN;
            #pragma unroll
            for (int l = 0; l < 12; l++) {
                int m = lane + 32 * l;
                s += row[m] * g_a[m];
            }
            s = warp_sum(s);
            if (lane == 0) g_w_hypo[gw] = s;
        } else {
            const int c = gw - NN;
            const float* row = g_ET + c * NN;
            #pragma unroll
            for (int l = 0; l < 12; l++) {
                int n = lane + 32 * l;
                s += row[n] * g_b[n];
            }
            s = warp_sum(s);
            if (lane == 0) g_w_hyper[c] = s;
        }
    }
    grid_barrier();

    // ===== P4: prototype partials ============================================
    if (blockIdx.x < 128) {
        const int mat = blockIdx.x >> 6;           // 0: Y/w_hyper, 1: X/w_hypo
        const int c = blockIdx.x & 63;
        const float* M  = mat ? X : Y;
        const float* wv = mat ? g_w_hypo : g_w_hyper;
        float* part     = mat ? g_xpart : g_hpart;
        const int r0 = c * 6;
        float acc0 = 0.f, acc1 = 0.f, acc2 = 0.f;
        #pragma unroll
        for (int r = 0; r < 6; r++) {
            const float wr = wv[r0 + r];
            const float* mp = M + (size_t)(r0 + r) * HH;
            acc0 += wr * mp[tid];
            acc1 += wr * mp[tid + 256];
            acc2 += wr * mp[tid + 512];
        }
        part[c * HH + tid]       = acc0;
        part[c * HH + tid + 256] = acc1;
        part[c * HH + tid + 512] = acc2;
    }
    grid_barrier();

    // ===== P5: combine partials -> prototypes ================================
    {
        const int g = blockIdx.x * 256 + tid;
        if (g < 2 * HH) {
            const int mat = (g >= HH);
            const int d = g - mat * HH;
            const float* part = mat ? g_xpart : g_hpart;
            float s = 0.f;
            #pragma unroll 8
            for (int c = 0; c < 64; c++) s += part[c * HH + d];
            if (mat) g_xp[d] = s;
            else     g_hp[d] = s;
        }
    }
    grid_barrier();

    // ===== P6: feats + classifier (block 0) ==================================
    if (blockIdx.x == 0) {
        __shared__ float sh[24];
        float p0 = 0.f, p1 = 0.f, p2 = 0.f;
        #pragma unroll
        for (int d = tid; d < HH; d += 256) {
            float hp = g_hp[d], xp = g_xp[d];
            float fd = hp - xp;
            float fm = hp * xp;
            p0 += W[d] * hp + W[HH + d] * xp + W[2 * HH + d] * fd + W[3 * HH + d] * fm;
            p1 += W[4 * HH + d] * hp + W[5 * HH + d] * xp + W[6 * HH + d] * fd + W[7 * HH + d] * fm;
            p2 += W[8 * HH + d] * hp + W[9 * HH + d] * xp + W[10 * HH + d] * fd + W[11 * HH + d] * fm;
        }
        p0 = warp_sum(p0); p1 = warp_sum(p1); p2 = warp_sum(p2);
        if (lane == 0) { sh[wid] = p0; sh[8 + wid] = p1; sh[16 + wid] = p2; }
        __syncthreads();
        if (tid == 0) {
            float s0 = 0.f, s1 = 0.f, s2 = 0.f;
            #pragma unroll
            for (int i = 0; i < 8; i++) { s0 += sh[i]; s1 += sh[8 + i]; s2 += sh[16 + i]; }
            out[0] = s0 + B[0];
            out[1] = s1 + B[1];
            out[2] = s2 + B[2];
        }
    }
}

// ---------------- host: weighted Lawson fit of odd tanh poly -----------------
// tanh(x) ~= s*(c0 + c1 v + ... + c6 v^6), s = x/4, v = s^2, x in [0,4].
static bool solve7(double A[7][7], double b[7], double c[7]) {
    for (int col = 0; col < 7; col++) {
        int p = col;
        for (int r = col + 1; r < 7; r++)
            if (fabs(A[r][col]) > fabs(A[p][col])) p = r;
        if (p != col) {
            for (int k = 0; k < 7; k++) { double t = A[col][k]; A[col][k] = A[p][k]; A[p][k] = t; }
            double t = b[col]; b[col] = b[p]; b[p] = t;
        }
        double d = A[col][col];
        if (fabs(d) < 1e-280) return false;
        for (int r = col + 1; r < 7; r++) {
            double f = A[r][col] / d;
            for (int k = col; k < 7; k++) A[r][k] -= f * A[col][k];
            b[r] -= f * b[col];
        }
    }
    for (int r = 6; r >= 0; r--) {
        double s = b[r];
        for (int k = r + 1; k < 7; k++) s -= A[r][k] * c[k];
        c[r] = s / A[r][r];
    }
    return true;
}

static Coef fit_tanh_poly() {
    const int M = 256;
    static double xs[M], t[M], w[M];
    double c[7] = {0};
    for (int i = 0; i < M; i++) {
        double x = 4.0 * (i + 0.5) / M;
        xs[i] = x; t[i] = tanh(x); w[i] = 1.0;
    }
    for (int it = 0; it < 40; it++) {
        double A[7][7] = {}, b[7] = {};
        for (int i = 0; i < M; i++) {
            double s = xs[i] * 0.25, s2 = s * s;
            double phi[7];
            phi[0] = s;
            for (int j = 1; j < 7; j++) phi[j] = phi[j - 1] * s2;
            for (int j = 0; j < 7; j++) {
                b[j] += w[i] * phi[j] * t[i];
                for (int k = 0; k < 7; k++) A[j][k] += w[i] * phi[j] * phi[k];
            }
        }
        double cn[7];
        if (!solve7(A, b, cn)) break;
        for (int j = 0; j < 7; j++) c[j] = cn[j];
        // Lawson reweight toward minimax
        double wsum = 0.0;
        for (int i = 0; i < M; i++) {
            double s = xs[i] * 0.25, s2 = s * s;
            double p = 0.0, ph = s;
            for (int j = 0; j < 7; j++) { p += c[j] * ph; ph *= s2; }
            double e = fabs(p - t[i]);
            w[i] *= (e + 1e-7);
            wsum += w[i];
        }
        double norm = (double)M / wsum;
        for (int i = 0; i < M; i++) w[i] *= norm;
    }
    Coef cf;
    for (int j = 0; j < 7; j++) cf.c[j] = (float)c[j];
    return cf;
}

// ---------------- launch ------------------------------------------------------
extern "C" void kernel_launch(void* const* d_in, const int* in_sizes, int n_in,
                              void* d_out, int out_size) {
    const float* X = (const float*)d_in[0];  // hypo_embeddings [384,768]
    const float* Y = (const float*)d_in[1];  // hyper_embeddings [384,768]
    const float* W = (const float*)d_in[2];  // W_cls [3,3072]
    const float* B = (const float*)d_in[3];  // b_cls [3]
    float* out = (float*)d_out;              // [3]

    static Coef cf;
    static bool fitted = false;
    if (!fitted) { cf = fit_tanh_poly(); fitted = true; }  // deterministic constants

    fused_kernel<<<NB, 256>>>(X, Y, W, B, out, cf);
}

// round 7
// speedup vs baseline: 1.1657x; 1.1657x over previous
#include <cuda_runtime.h>
#include <cstdint>
#include <cstring>
#include <math.h>

#define NN 384
#define HH 768
#define NB 576                              // 4 blocks/SM x 144; <= 592 co-resident
#define INV_SQRT_H 0.03608439182435161f     // 1/sqrt(768)
#define INV_N      0.0026041666666666665f   // 1/384
#define POLY_KK0 9                          // f16x2 words kk>=9 (k>=18) use poly path

struct CoefH { uint32_t h[7]; };            // f16x2-replicated poly coeffs (s-basis)

// ---------------- scratch (device globals; no allocation allowed) ----------
__device__ float g_P [4 * NN * NN];         // k-split tanh-sum partials   2.25 MB
__device__ float g_E [NN * NN];             // exp(att)                    576 KB
__device__ float g_ET[NN * NN];             // exp(att) transposed         576 KB
__device__ float g_rinv[NN], g_cinv[NN];
__device__ float g_a[NN], g_b[NN];
__device__ float g_w_hypo[NN], g_w_hyper[NN];
__device__ float g_hpart[64 * HH], g_xpart[64 * HH];
__device__ float g_hp[HH], g_xp[HH];
__device__ unsigned g_arrive;               // monotonic barrier counter (replay-safe)

// ---------------- f16x2 helpers ----------------
__device__ __forceinline__ uint32_t packh2(float a, float b) {
    uint32_t d;
    asm("cvt.rn.f16x2.f32 %0, %1, %2;" : "=r"(d) : "f"(b), "f"(a));
    return d;
}
__device__ __forceinline__ uint32_t hmul2(uint32_t a, uint32_t b) {
    uint32_t d;
    asm("mul.rn.f16x2 %0, %1, %2;" : "=r"(d) : "r"(a), "r"(b));
    return d;
}
__device__ __forceinline__ uint32_t hadd2(uint32_t a, uint32_t b) {
    uint32_t d;
    asm("add.rn.f16x2 %0, %1, %2;" : "=r"(d) : "r"(a), "r"(b));
    return d;
}
__device__ __forceinline__ uint32_t hfma2(uint32_t a, uint32_t b, uint32_t c) {
    uint32_t d;
    asm("fma.rn.f16x2 %0, %1, %2, %3;" : "=r"(d) : "r"(a), "r"(b), "r"(c));
    return d;
}
__device__ __forceinline__ uint32_t hmin2(uint32_t a, uint32_t b) {
    uint32_t d;
    asm("min.f16x2 %0, %1, %2;" : "=r"(d) : "r"(a), "r"(b));
    return d;
}
__device__ __forceinline__ uint32_t hmax2(uint32_t a, uint32_t b) {
    uint32_t d;
    asm("max.f16x2 %0, %1, %2;" : "=r"(d) : "r"(a), "r"(b));
    return d;
}
__device__ __forceinline__ uint32_t htanh2(uint32_t a) {
    uint32_t d;
    asm("tanh.approx.f16x2 %0, %1;" : "=r"(d) : "r"(a));
    return d;
}
__device__ __forceinline__ float h2sum(uint32_t s) {
    float lo, hi;
    asm("{ .reg .b16 l, h;\n\t"
        "  mov.b32 {l, h}, %2;\n\t"
        "  cvt.f32.f16 %0, l;\n\t"
        "  cvt.f32.f16 %1, h; }"
        : "=f"(lo), "=f"(hi) : "r"(s));
    return lo + hi;
}

__device__ __forceinline__ float warp_sum(float v) {
    #pragma unroll
    for (int o = 16; o; o >>= 1) v += __shfl_xor_sync(0xffffffffu, v, o);
    return v;
}

// Software grid barrier. Monotonic counter -> safe across CUDA-graph replays.
__device__ __forceinline__ void grid_barrier() {
    __syncthreads();
    __threadfence();
    if (threadIdx.x == 0) {
        unsigned my = atomicAdd(&g_arrive, 1u) + 1u;
        unsigned target = ((my + NB - 1u) / NB) * NB;
        unsigned cur;
        do {
            asm volatile("ld.global.acquire.gpu.b32 %0, [%1];"
                         : "=r"(cur) : "l"(&g_arrive));
        } while ((int)(cur - target) < 0);
    }
    __syncthreads();
    __threadfence();
}

// ---------------- single fused kernel ----------------------------------------
__global__ __launch_bounds__(256, 4) void fused_kernel(const float* __restrict__ X,
                                                       const float* __restrict__ Y,
                                                       const float* __restrict__ W,
                                                       const float* __restrict__ B,
                                                       float* __restrict__ out,
                                                       CoefH cf) {
    __shared__ uint32_t sX2[32][17];    // f16x2 tiles; X words kk>=POLY_KK0 prescaled x0.25
    __shared__ uint32_t sY2[32][17];

    const int tid = threadIdx.x;
    const int lane = tid & 31;
    const int wid = tid >> 5;

    const uint32_t C0 = cf.h[0], C1 = cf.h[1], C2 = cf.h[2], C3 = cf.h[3];
    const uint32_t C4 = cf.h[4], C5 = cf.h[5], C6 = cf.h[6];
    const uint32_t ONE2 = 0x3c003c00u, NONE2 = 0xbc00bc00u;   // +1/-1 f16x2

    // ===== Phase 0: k-split partials of sum_h tanh(X[n,h]*Y[m,h]) ===========
    // 576 blocks = 144 tiles (32x32) x 4 k-chunks of 192. 16x16 threads, 2x2 micro.
    // Per 32-k chunk: k 0..17 via hw tanh2 (XU pipe); k 18..31 via odd-poly
    // tanh in f16x2 on the FMA pipe (s = t/4 folded into the X-tile packing).
    {
        const int tile = blockIdx.x % 144;
        const int kc   = blockIdx.x / 144;       // 0..3
        const int tx = tid & 15;
        const int ty = tid >> 4;
        const int bi = (tile / 12) * 32;         // hypo rows
        const int bj = (tile % 12) * 32;         // hyper rows
        const int lr = tid >> 3;                 // 0..31 load row
        const int lf = (tid & 7) << 2;           // float offset 0..28
        const int lh = (tid & 7) << 1;           // half2 word offset 0..14
        const float scA = (lh     >= POLY_KK0) ? 0.25f : 1.0f;
        const float scB = (lh + 1 >= POLY_KK0) ? 0.25f : 1.0f;

        float a00 = 0.f, a01 = 0.f, a10 = 0.f, a11 = 0.f;

        const int kbeg = kc * 192, kend = kbeg + 192;
        #pragma unroll 1
        for (int k0 = kbeg; k0 < kend; k0 += 32) {
            float4 vx = *(const float4*)(X + (size_t)(bi + lr) * HH + k0 + lf);
            float4 vy = *(const float4*)(Y + (size_t)(bj + lr) * HH + k0 + lf);
            sX2[lr][lh]     = packh2(vx.x * scA, vx.y * scA);
            sX2[lr][lh + 1] = packh2(vx.z * scB, vx.w * scB);
            sY2[lr][lh]     = packh2(vy.x, vy.y);
            sY2[lr][lh + 1] = packh2(vy.z, vy.w);
            __syncthreads();

            // --- hw-tanh2 lanes: kk = 0..8 (k 0..17), two chains for ILP ---
            uint32_t ch00 = 0, ch01 = 0, ch10 = 0, ch11 = 0;   // even kk
            uint32_t cd00 = 0, cd01 = 0, cd10 = 0, cd11 = 0;   // odd kk
            #pragma unroll
            for (int kk = 0; kk < POLY_KK0; kk++) {
                uint32_t x0 = sX2[2 * ty][kk],     x1 = sX2[2 * ty + 1][kk];
                uint32_t y0 = sY2[2 * tx][kk],     y1 = sY2[2 * tx + 1][kk];
                if (kk & 1) {
                    cd00 = hadd2(cd00, htanh2(hmul2(x0, y0)));
                    cd01 = hadd2(cd01, htanh2(hmul2(x0, y1)));
                    cd10 = hadd2(cd10, htanh2(hmul2(x1, y0)));
                    cd11 = hadd2(cd11, htanh2(hmul2(x1, y1)));
                } else {
                    ch00 = hadd2(ch00, htanh2(hmul2(x0, y0)));
                    ch01 = hadd2(ch01, htanh2(hmul2(x0, y1)));
                    ch10 = hadd2(ch10, htanh2(hmul2(x1, y0)));
                    ch11 = hadd2(ch11, htanh2(hmul2(x1, y1)));
                }
            }

            // --- poly lanes: kk = 9..15 (k 18..31), FMA pipe ---
            uint32_t pd00 = 0, pd01 = 0, pd10 = 0, pd11 = 0;
            #pragma unroll
            for (int kk = POLY_KK0; kk < 16; kk++) {
                uint32_t x0 = sX2[2 * ty][kk],     x1 = sX2[2 * ty + 1][kk];  // x/4
                uint32_t y0 = sY2[2 * tx][kk],     y1 = sY2[2 * tx + 1][kk];
                #define PACC(pd, xx, yy) do {                              \
                    uint32_t s_ = hmul2((xx), (yy));                       \
                    s_ = hmin2(hmax2(s_, NONE2), ONE2);                    \
                    uint32_t v_ = hmul2(s_, s_);                           \
                    uint32_t H_ = C6;                                      \
                    H_ = hfma2(H_, v_, C5); H_ = hfma2(H_, v_, C4);        \
                    H_ = hfma2(H_, v_, C3); H_ = hfma2(H_, v_, C2);        \
                    H_ = hfma2(H_, v_, C1); H_ = hfma2(H_, v_, C0);        \
                    (pd) = hfma2(H_, s_, (pd));                            \
                } while (0)
                PACC(pd00, x0, y0);
                PACC(pd01, x0, y1);
                PACC(pd10, x1, y0);
                PACC(pd11, x1, y1);
                #undef PACC
            }

            a00 += h2sum(hadd2(hadd2(ch00, cd00), pd00));
            a01 += h2sum(hadd2(hadd2(ch01, cd01), pd01));
            a10 += h2sum(hadd2(hadd2(ch10, cd10), pd10));
            a11 += h2sum(hadd2(hadd2(ch11, cd11), pd11));
            __syncthreads();
        }

        float* P = g_P + (size_t)kc * NN * NN;
        const int i = bi + 2 * ty, j = bj + 2 * tx;
        P[i * NN + j]           = a00;
        P[i * NN + j + 1]       = a01;
        P[(i + 1) * NN + j]     = a10;
        P[(i + 1) * NN + j + 1] = a11;
    }
    grid_barrier();

    // ===== Phase 0.5: combine k-partials -> E = exp(att), plus transpose ====
    {
        const int idx = blockIdx.x * 256 + tid;      // exactly covers 384*384
        float s = g_P[idx] + g_P[NN * NN + idx] + g_P[2 * NN * NN + idx] + g_P[3 * NN * NN + idx];
        float e = __expf(s * INV_SQRT_H);            // |att|<=27.7 -> fp32-safe
        g_E[idx] = e;
        const int i = idx / NN, j = idx - (idx / NN) * NN;
        g_ET[j * NN + i] = e;
    }
    grid_barrier();

    const int gw = blockIdx.x * 8 + wid;     // global warp id

    // ===== P1: inverse row/col sums of E (warp per row; coalesced) ==========
    if (gw < 2 * NN) {
        const float* row = (gw < NN) ? (g_E + gw * NN) : (g_ET + (gw - NN) * NN);
        float s = 0.f;
        #pragma unroll
        for (int l = 0; l < 12; l++) s += row[lane + 32 * l];
        s = warp_sum(s);
        if (lane == 0) {
            if (gw < NN) g_rinv[gw] = 1.0f / s;
            else         g_cinv[gw - NN] = 1.0f / s;
        }
    }
    grid_barrier();

    // ===== P2: typicalness factors (pre-scaled) ==============================
    if (gw < 2 * NN) {
        float s = 0.f;
        if (gw < NN) {
            const float* row = g_E + gw * NN;
            #pragma unroll
            for (int l = 0; l < 12; l++) {
                int m = lane + 32 * l;
                s += row[m] * g_cinv[m];
            }
            s = warp_sum(s);
            if (lane == 0) g_b[gw] = s * g_rinv[gw] * INV_N;
        } else {
            const int c = gw - NN;
            const float* row = g_ET + c * NN;
            #pragma unroll
            for (int l = 0; l < 12; l++) {
                int n = lane + 32 * l;
                s += row[n] * g_rinv[n];
            }
            s = warp_sum(s);
            if (lane == 0) g_a[c] = s * g_cinv[c] * INV_N;
        }
    }
    grid_barrier();

    // ===== P3: pooling weights ===============================================
    if (gw < 2 * NN) {
        float s = 0.f;
        if (gw < NN) {
            const float* row = g_E + gw * NN;
            #pragma unroll
            for (int l = 0; l < 12; l++) {
                int m = lane + 32 * l;
                s += row[m] * g_a[m];
            }
            s = warp_sum(s);
            if (lane == 0) g_w_hypo[gw] = s;
        } else {
            const int c = gw - NN;
            const float* row = g_ET + c * NN;
            #pragma unroll
            for (int l = 0; l < 12; l++) {
                int n = lane + 32 * l;
                s += row[n] * g_b[n];
            }
            s = warp_sum(s);
            if (lane == 0) g_w_hyper[c] = s;
        }
    }
    grid_barrier();

    // ===== P4: prototype partials ============================================
    if (blockIdx.x < 128) {
        const int mat = blockIdx.x >> 6;           // 0: Y/w_hyper, 1: X/w_hypo
        const int c = blockIdx.x & 63;
        const float* M  = mat ? X : Y;
        const float* wv = mat ? g_w_hypo : g_w_hyper;
        float* part     = mat ? g_xpart : g_hpart;
        const int r0 = c * 6;
        float acc0 = 0.f, acc1 = 0.f, acc2 = 0.f;
        #pragma unroll
        for (int r = 0; r < 6; r++) {
            const float wr = wv[r0 + r];
            const float* mp = M + (size_t)(r0 + r) * HH;
            acc0 += wr * mp[tid];
            acc1 += wr * mp[tid + 256];
            acc2 += wr * mp[tid + 512];
        }
        part[c * HH + tid]       = acc0;
        part[c * HH + tid + 256] = acc1;
        part[c * HH + tid + 512] = acc2;
    }
    grid_barrier();

    // ===== P5: combine partials -> prototypes ================================
    {
        const int g = blockIdx.x * 256 + tid;
        if (g < 2 * HH) {
            const int mat = (g >= HH);
            const int d = g - mat * HH;
            const float* part = mat ? g_xpart : g_hpart;
            float s = 0.f;
            #pragma unroll 8
            for (int c = 0; c < 64; c++) s += part[c * HH + d];
            if (mat) g_xp[d] = s;
            else     g_hp[d] = s;
        }
    }
    grid_barrier();

    // ===== P6: feats + classifier (block 0) ==================================
    if (blockIdx.x == 0) {
        __shared__ float sh[24];
        float p0 = 0.f, p1 = 0.f, p2 = 0.f;
        #pragma unroll
        for (int d = tid; d < HH; d += 256) {
            float hp = g_hp[d], xp = g_xp[d];
            float fd = hp - xp;
            float fm = hp * xp;
            p0 += W[d] * hp + W[HH + d] * xp + W[2 * HH + d] * fd + W[3 * HH + d] * fm;
            p1 += W[4 * HH + d] * hp + W[5 * HH + d] * xp + W[6 * HH + d] * fd + W[7 * HH + d] * fm;
            p2 += W[8 * HH + d] * hp + W[9 * HH + d] * xp + W[10 * HH + d] * fd + W[11 * HH + d] * fm;
        }
        p0 = warp_sum(p0); p1 = warp_sum(p1); p2 = warp_sum(p2);
        if (lane == 0) { sh[wid] = p0; sh[8 + wid] = p1; sh[16 + wid] = p2; }
        __syncthreads();
        if (tid == 0) {
            float s0 = 0.f, s1 = 0.f, s2 = 0.f;
            #pragma unroll
            for (int i = 0; i < 8; i++) { s0 += sh[i]; s1 += sh[8 + i]; s2 += sh[16 + i]; }
            out[0] = s0 + B[0];
            out[1] = s1 + B[1];
            out[2] = s2 + B[2];
        }
    }
}

// ---------------- host: weighted Lawson fit of odd tanh poly -----------------
// tanh(x) ~= s*(c0 + c1 v + ... + c6 v^6), s = x/4, v = s^2, x in [0,4].
static bool solve7(double A[7][7], double b[7], double c[7]) {
    for (int col = 0; col < 7; col++) {
        int p = col;
        for (int r = col + 1; r < 7; r++)
            if (fabs(A[r][col]) > fabs(A[p][col])) p = r;
        if (p != col) {
            for (int k = 0; k < 7; k++) { double t = A[col][k]; A[col][k] = A[p][k]; A[p][k] = t; }
            double t = b[col]; b[col] = b[p]; b[p] = t;
        }
        double d = A[col][col];
        if (fabs(d) < 1e-280) return false;
        for (int r = col + 1; r < 7; r++) {
            double f = A[r][col] / d;
            for (int k = col; k < 7; k++) A[r][k] -= f * A[col][k];
            b[r] -= f * b[col];
        }
    }
    for (int r = 6; r >= 0; r--) {
        double s = b[r];
        for (int k = r + 1; k < 7; k++) s -= A[r][k] * c[k];
        c[r] = s / A[r][r];
    }
    return true;
}

static uint16_t f2h(float f) {
    uint32_t x; memcpy(&x, &f, 4);
    uint32_t sign = (x >> 16) & 0x8000u;
    int exp = (int)((x >> 23) & 0xffu) - 127 + 15;
    uint32_t man = x & 0x7fffffu;
    if (exp <= 0) return (uint16_t)sign;
    if (exp >= 31) return (uint16_t)(sign | 0x7c00u);
    uint32_t h = sign | ((uint32_t)exp << 10) | (man >> 13);
    uint32_t rem = man & 0x1fffu;
    if (rem > 0x1000u || (rem == 0x1000u && (h & 1u))) h++;
    return (uint16_t)h;
}

static CoefH fit_tanh_poly_h() {
    const int M = 256;
    static double xs[M], t[M], w[M];
    double c[7] = {0};
    for (int i = 0; i < M; i++) {
        double x = 4.0 * (i + 0.5) / M;
        xs[i] = x; t[i] = tanh(x); w[i] = 1.0;
    }
    for (int it = 0; it < 40; it++) {
        double A[7][7] = {}, b[7] = {};
        for (int i = 0; i < M; i++) {
            double s = xs[i] * 0.25, s2 = s * s;
            double phi[7];
            phi[0] = s;
            for (int j = 1; j < 7; j++) phi[j] = phi[j - 1] * s2;
            for (int j = 0; j < 7; j++) {
                b[j] += w[i] * phi[j] * t[i];
                for (int k = 0; k < 7; k++) A[j][k] += w[i] * phi[j] * phi[k];
            }
        }
        double cn[7];
        if (!solve7(A, b, cn)) break;
        for (int j = 0; j < 7; j++) c[j] = cn[j];
        double wsum = 0.0;
        for (int i = 0; i < M; i++) {
            double s = xs[i] * 0.25, s2 = s * s;
            double p = 0.0, ph = s;
            for (int j = 0; j < 7; j++) { p += c[j] * ph; ph *= s2; }
            double e = fabs(p - t[i]);
            w[i] *= (e + 1e-7);
            wsum += w[i];
        }
        double norm = (double)M / wsum;
        for (int i = 0; i < M; i++) w[i] *= norm;
    }
    CoefH cf;
    for (int j = 0; j < 7; j++) {
        uint16_t hh = f2h((float)c[j]);
        cf.h[j] = ((uint32_t)hh << 16) | hh;
    }
    return cf;
}

// ---------------- launch ------------------------------------------------------
extern "C" void kernel_launch(void* const* d_in, const int* in_sizes, int n_in,
                              void* d_out, int out_size) {
    const float* X = (const float*)d_in[0];  // hypo_embeddings [384,768]
    const float* Y = (const float*)d_in[1];  // hyper_embeddings [384,768]
    const float* W = (const float*)d_in[2];  // W_cls [3,3072]
    const float* B = (const float*)d_in[3];  // b_cls [3]
    float* out = (float*)d_out;              // [3]

    static CoefH cf;
    static bool fitted = false;
    if (!fitted) { cf = fit_tanh_poly_h(); fitted = true; }  // deterministic constants

    fused_kernel<<<NB, 256>>>(X, Y, W, B, out, cf);
}